// round 15
// baseline (speedup 1.0000x reference)
#include <cuda_runtime.h>

// GLoss fused, correlation form, cp.async 4-stage ring, 32-row tiles,
// 256 threads x float2 per thread (double warps/SM vs the float4 variant).
//
// Identity (validated R6-R14):
//   G = 16*S - B - 4*(C_E + C_S + C_SE + C_SW),  B = sum w(p) d[p]^2,
//   w = 3*ry + 3*cx - ry*cx.  Full-res + pixel loss: WG*(24S - B - 4C).
//   Half-res: WGD*(16S - B - 4C) on dd = maxpool2(o) - maxpool2(t).

#define IMG   1024
#define HIMG  512
#define NIMG  8
#define ROWS  32
#define NITER 16                      // pairs 0..15 owned
#define GRIDY (IMG / ROWS)            // 32
#define NBLK  (2 * GRIDY * NIMG)      // 512
#define THR   256

#define WG  (1.0f / 67108864.0f)      // 1/(8*8*1024*1024)
#define WGD (1.0f / 16777216.0f)      // 1/(8*8*512*512)

__device__ float g_part[NBLK];
__device__ unsigned int g_count = 0;

__device__ __forceinline__ float bw(int y, int x, int n) {
    int ry = (y == 0) + (y == n - 1);
    int cx = (x == 0) + (x == n - 1);
    return (float)(3 * ry + 3 * cx - ry * cx);
}

__device__ __forceinline__ float max4(float a, float b, float c, float d) {
    return fmaxf(fmaxf(a, b), fmaxf(c, d));
}

__device__ __forceinline__ void cp_async8(void* sdst, const void* gsrc) {
    unsigned s = (unsigned)__cvta_generic_to_shared(sdst);
    asm volatile("cp.async.ca.shared.global [%0], [%1], 8;"
                 :: "r"(s), "l"(gsrc) : "memory");
}

__global__ __launch_bounds__(THR, 4) void gloss_corr(
    const float* __restrict__ img_o,
    const float* __restrict__ img_t,
    float* __restrict__ out)
{
    // 4-stage ring: [stage][slot][tid]; slot 0/1 = o rows, 2/3 = t rows. 32 KB.
    __shared__ float2 stg[4][4][THR];
    __shared__ float red[8];
    __shared__ double dred[8];
    __shared__ unsigned int s_last;

    const int tid  = threadIdx.x;
    const int lane = tid & 31;
    const int ry0  = blockIdx.y * ROWS;
    const size_t base = (size_t)blockIdx.z * IMG * IMG;
    const int gx0 = blockIdx.x * 512 + (tid << 1);
    const int hx0 = gx0 >> 1;

    const bool isR      = (lane == 31);
    const bool edge_ld  = isR && (gx0 + 2 < IMG);
    const bool col_edge = (gx0 == 0) | (gx0 + 2 == IMG);
    const bool okL      = (ry0 + ROWS < IMG);     // last pair (16) in image?

    const float* po_base = img_o + base + gx0;
    const float* pt_base = img_t + base + gx0;
    const float* poe = img_o + base + gx0 + 2;    // only deref'd when edge_ld
    const float* pte = img_t + base + gx0 + 2;
    const float2 z2 = make_float2(0.f, 0.f);

    // ---- carried diffs for current pair ----
    float2 d0, d1;
    float  dd;
    float  eR0 = 0.f, eR1 = 0.f, eddR = 0.f;

    // prologue: pair 0 via direct LDG + convert
    {
        const size_t roff = (size_t)ry0 * IMG;
        float2 o0 = *(const float2*)(po_base + roff);
        float2 o1 = *(const float2*)(po_base + roff + IMG);
        float2 t0 = *(const float2*)(pt_base + roff);
        float2 t1 = *(const float2*)(pt_base + roff + IMG);
        d0 = make_float2(o0.x - t0.x, o0.y - t0.y);
        d1 = make_float2(o1.x - t1.x, o1.y - t1.y);
        dd = max4(o0.x, o0.y, o1.x, o1.y) - max4(t0.x, t0.y, t1.x, t1.y);
        if (edge_ld) {
            float2 a0 = *(const float2*)(poe + roff);
            float2 a1 = *(const float2*)(poe + roff + IMG);
            float2 b0 = *(const float2*)(pte + roff);
            float2 b1 = *(const float2*)(pte + roff + IMG);
            eR0  = a0.x - b0.x;
            eR1  = a1.x - b1.x;
            eddR = max4(a0.x, a0.y, a1.x, a1.y) - max4(b0.x, b0.y, b1.x, b1.y);
        }
    }

    // prologue: queue pairs 1..3 (always in image) as groups g0..g2
    #pragma unroll
    for (int p = 1; p <= 3; p++) {
        const size_t roff = (size_t)(ry0 + 2 * p) * IMG;
        cp_async8(&stg[p & 3][0][tid], po_base + roff);
        cp_async8(&stg[p & 3][1][tid], po_base + roff + IMG);
        cp_async8(&stg[p & 3][2][tid], pt_base + roff);
        cp_async8(&stg[p & 3][3][tid], pt_base + roff + IMG);
        asm volatile("cp.async.commit_group;" ::: "memory");
    }

    float sa = 0.f, ca0 = 0.f, ca1 = 0.f, ca2 = 0.f, ba = 0.f;
    float sh = 0.f, ch0 = 0.f, ch1 = 0.f, bh = 0.f;
    float2 dprev = z2;
    float  ddprev = 0.f;
    float  pnd1 = 0.f, pndd = 0.f;

    #pragma unroll 2
    for (int j = 0; j < NITER; j++) {             // pairs 0..15, all owned
        const int gy0 = ry0 + 2 * j;
        const int gy1 = gy0 + 1;

        // ---- 1. queue pair j+4 (empty commit keeps group counting uniform) ----
        {
            const int p = j + 4;
            if (p < NITER || (p == NITER && okL)) {
                const size_t roff = (size_t)(ry0 + 2 * p) * IMG;
                cp_async8(&stg[p & 3][0][tid], po_base + roff);
                cp_async8(&stg[p & 3][1][tid], po_base + roff + IMG);
                cp_async8(&stg[p & 3][2][tid], pt_base + roff);
                cp_async8(&stg[p & 3][3][tid], pt_base + roff + IMG);
            }
            asm volatile("cp.async.commit_group;" ::: "memory");
        }

        // edge raws for pair j+1 (lane 31; mostly L1/L2 hits)
        float2 ea0 = z2, ea1 = z2, eb0 = z2, eb1 = z2;
        {
            const int ng = ry0 + 2 * (j + 1);
            if (edge_ld && (j < NITER - 1 || okL)) {
                const size_t roff = (size_t)ng * IMG;
                ea0 = *(const float2*)(poe + roff);
                ea1 = *(const float2*)(poe + roff + IMG);
                eb0 = *(const float2*)(pte + roff);
                eb1 = *(const float2*)(pte + roff + IMG);
            }
        }

        // ---- 2. +1 neighbors via shuffle ----
        float t;
        t = __shfl_down_sync(0xFFFFFFFFu, d0.x, 1); float nd0 = isR ? eR0  : t;
        t = __shfl_down_sync(0xFFFFFFFFu, d1.x, 1); float nd1 = isR ? eR1  : t;
        t = __shfl_down_sync(0xFFFFFFFFu, dd,   1); float ndd = isR ? eddR : t;

        // ---- 3. FMA block (float2 width of the validated math) ----
        // cross terms with previous pair (dprev = 0 at j=0 -> no-op)
        ca0 = fmaf(dprev.x, d0.x, ca0); ca0 = fmaf(dprev.y, d0.y, ca0);   // S
        ca1 = fmaf(dprev.x, d0.y, ca1); ca1 = fmaf(dprev.y, nd0,  ca1);   // SE
        ca2 = fmaf(dprev.y, d0.x, ca2); ca2 = fmaf(pnd1,    d0.y, ca2);   // SW

        ch0 = fmaf(ddprev, dd,  ch0);                                     // S
        ch1 = fmaf(ddprev, ndd, ch1);                                     // SE
        ch0 = fmaf(pndd,   dd,  ch0);                                     // SW

        // owned terms
        sa = fmaf(d0.x, d0.x, sa); sa = fmaf(d0.y, d0.y, sa);
        sa = fmaf(d1.x, d1.x, sa); sa = fmaf(d1.y, d1.y, sa);

        ca0 = fmaf(d0.x, d0.y, ca0); ca0 = fmaf(d0.y, nd0, ca0);          // E row0
        ca1 = fmaf(d1.x, d1.y, ca1); ca1 = fmaf(d1.y, nd1, ca1);          // E row1
        ca2 = fmaf(d0.x, d1.x, ca2); ca2 = fmaf(d0.y, d1.y, ca2);         // S pair
        ca0 = fmaf(d0.x, d1.y, ca0); ca0 = fmaf(d0.y, nd1, ca0);          // SE pair
        ca1 = fmaf(d0.y, d1.x, ca1); ca1 = fmaf(nd0,  d1.y, ca1);         // SW pair

        sh  = fmaf(dd, dd,  sh);
        ch1 = fmaf(dd, ndd, ch1);                                         // E half

        if (col_edge | (gy0 == 0) | (gy1 == IMG - 1)) {
            ba = fmaf(bw(gy0, gx0,     IMG) * d0.x, d0.x, ba);
            ba = fmaf(bw(gy0, gx0 + 1, IMG) * d0.y, d0.y, ba);
            ba = fmaf(bw(gy1, gx0,     IMG) * d1.x, d1.x, ba);
            ba = fmaf(bw(gy1, gx0 + 1, IMG) * d1.y, d1.y, ba);
        }
        {
            const int hgy = (ry0 >> 1) + j;
            if (col_edge | (hgy == 0) | (hgy == HIMG - 1)) {
                bh = fmaf(bw(hgy, hx0, HIMG) * dd, dd, bh);
            }
        }

        // ---- 4. wait for pair j+1 and convert from smem ----
        asm volatile("cp.async.wait_group 3;" ::: "memory");
        float2 pd0, pd1;
        float  pdd;
        if (j < NITER - 1 || okL) {
            const int s = (j + 1) & 3;
            float2 o0 = stg[s][0][tid], o1 = stg[s][1][tid];
            float2 t0 = stg[s][2][tid], t1 = stg[s][3][tid];
            pd0 = make_float2(o0.x - t0.x, o0.y - t0.y);
            pd1 = make_float2(o1.x - t1.x, o1.y - t1.y);
            pdd = max4(o0.x, o0.y, o1.x, o1.y) - max4(t0.x, t0.y, t1.x, t1.y);
        } else {
            pd0 = pd1 = z2;
            pdd = 0.f;
        }
        float peR0  = ea0.x - eb0.x;
        float peR1  = ea1.x - eb1.x;
        float peddR = max4(ea0.x, ea0.y, ea1.x, ea1.y)
                    - max4(eb0.x, eb0.y, eb1.x, eb1.y);

        // ---- 5. rotate ----
        dprev = d1; ddprev = dd; pnd1 = nd1; pndd = ndd;
        d0 = pd0; d1 = pd1; dd = pdd;
        eR0 = peR0; eR1 = peR1; eddR = peddR;
    }

    // ---- peeled last pair: cross terms only ----
    {
        float t;
        t = __shfl_down_sync(0xFFFFFFFFu, d0.x, 1); float nd0 = isR ? eR0  : t;
        t = __shfl_down_sync(0xFFFFFFFFu, dd,   1); float ndd = isR ? eddR : t;

        ca0 = fmaf(dprev.x, d0.x, ca0); ca0 = fmaf(dprev.y, d0.y, ca0);   // S
        ca1 = fmaf(dprev.x, d0.y, ca1); ca1 = fmaf(dprev.y, nd0,  ca1);   // SE
        ca2 = fmaf(dprev.y, d0.x, ca2); ca2 = fmaf(pnd1,    d0.y, ca2);   // SW

        ch0 = fmaf(ddprev, dd,  ch0);                                     // S
        ch1 = fmaf(ddprev, ndd, ch1);                                     // SE
        ch0 = fmaf(pndd,   dd,  ch0);                                     // SW
    }

    // ---------------- block reduction + last-block finalize ----------------
    float ca = ca0 + ca1 + ca2;
    float ch = ch0 + ch1;
    float val = (24.f * sa - ba - 4.f * ca) * WG
              + (16.f * sh - bh - 4.f * ch) * WGD;
    #pragma unroll
    for (int off = 16; off; off >>= 1)
        val += __shfl_down_sync(0xFFFFFFFFu, val, off);
    int warp = tid >> 5;
    if (lane == 0) red[warp] = val;
    __syncthreads();
    if (tid == 0) {
        float s = 0.f;
        #pragma unroll
        for (int w = 0; w < 8; w++) s += red[w];
        int bid = (blockIdx.z * GRIDY + blockIdx.y) * 2 + blockIdx.x;
        g_part[bid] = s;
        __threadfence();
        unsigned old = atomicAdd(&g_count, 1u);
        s_last = (old == NBLK - 1) ? 1u : 0u;
    }
    __syncthreads();

    if (s_last) {
        double s = 0.0;
        #pragma unroll
        for (int i = tid; i < NBLK; i += THR)
            s += (double)g_part[i];
        #pragma unroll
        for (int off = 16; off; off >>= 1)
            s += __shfl_down_sync(0xFFFFFFFFu, s, off);
        if (lane == 0) dred[warp] = s;
        __syncthreads();
        if (tid == 0) {
            double tot = 0.0;
            #pragma unroll
            for (int w = 0; w < 8; w++) tot += dred[w];
            out[0] = (float)tot;
            g_count = 0;   // reset for next graph replay
        }
    }
}

extern "C" void kernel_launch(void* const* d_in, const int* in_sizes, int n_in,
                              void* d_out, int out_size) {
    const float* img_o = (const float*)d_in[0];
    const float* img_t = (const float*)d_in[1];
    dim3 grid(2, GRIDY, NIMG);
    gloss_corr<<<grid, THR>>>(img_o, img_t, (float*)d_out);
}

// round 16
// speedup vs baseline: 1.1045x; 1.1045x over previous
#include <cuda_runtime.h>

// GLoss fused, correlation form, cp.async 4-stage ring, 32-row tiles,
// packed fp32x2 (FFMA2) arithmetic for the correlation sums.
//
// Identity (validated R6-R15):
//   G = 16*S - B - 4*(C_E + C_S + C_SE + C_SW),  B = sum w(p) d[p]^2,
//   w = 3*ry + 3*cx - ry*cx.  Full-res + pixel loss: WG*(24S - B - 4C).
//   Half-res: WGD*(16S - B - 4C) on dd = maxpool2(o) - maxpool2(t).
//
// Block = 128 threads = 512 cols (float4/thread), streams 17 row pairs
// (32 owned + 2 halo). Pair j+4 prefetched via cp.async into a 4-stage
// smem ring; pair j+1 converted from smem at iteration end.
// Correlation FMAs run as fma.rn.f32x2 (2 lanes/instr) -> ~25% fewer issues.

#define IMG   1024
#define HIMG  512
#define NIMG  8
#define ROWS  32
#define NITER 16                      // pairs 0..15 owned
#define GRIDY (IMG / ROWS)            // 32
#define NBLK  (2 * GRIDY * NIMG)      // 512

#define WG  (1.0f / 67108864.0f)      // 1/(8*8*1024*1024)
#define WGD (1.0f / 16777216.0f)      // 1/(8*8*512*512)

typedef unsigned long long u64;

__device__ float g_part[NBLK];
__device__ unsigned int g_count = 0;

__device__ __forceinline__ float bw(int y, int x, int n) {
    int ry = (y == 0) + (y == n - 1);
    int cx = (x == 0) + (x == n - 1);
    return (float)(3 * ry + 3 * cx - ry * cx);
}

__device__ __forceinline__ float max4(float a, float b, float c, float d) {
    return fmaxf(fmaxf(a, b), fmaxf(c, d));
}

__device__ __forceinline__ u64 pk2(float lo, float hi) {
    u64 r;
    asm("mov.b64 %0, {%1, %2};" : "=l"(r) : "f"(lo), "f"(hi));
    return r;
}

__device__ __forceinline__ void upk2(u64 v, float& lo, float& hi) {
    asm("mov.b64 {%0, %1}, %2;" : "=f"(lo), "=f"(hi) : "l"(v));
}

__device__ __forceinline__ u64 fma2(u64 a, u64 b, u64 c) {
    u64 r;
    asm("fma.rn.f32x2 %0, %1, %2, %3;" : "=l"(r) : "l"(a), "l"(b), "l"(c));
    return r;
}

__device__ __forceinline__ void cp_async16(void* sdst, const void* gsrc) {
    unsigned s = (unsigned)__cvta_generic_to_shared(sdst);
    asm volatile("cp.async.ca.shared.global [%0], [%1], 16;"
                 :: "r"(s), "l"(gsrc) : "memory");
}

__global__ __launch_bounds__(128, 4) void gloss_corr(
    const float* __restrict__ img_o,
    const float* __restrict__ img_t,
    float* __restrict__ out)
{
    // 4-stage ring: [stage][slot][tid]; slot 0/1 = o rows, 2/3 = t rows. 32 KB.
    __shared__ float4 stg[4][4][128];
    __shared__ float red[4];
    __shared__ double dred[4];
    __shared__ unsigned int s_last;

    const int tid  = threadIdx.x;
    const int lane = tid & 31;
    const int ry0  = blockIdx.y * ROWS;
    const size_t base = (size_t)blockIdx.z * IMG * IMG;
    const int gx0 = blockIdx.x * 512 + (tid << 2);
    const int hx0 = gx0 >> 1;

    const bool isR      = (lane == 31);
    const bool edge_ld  = isR && (gx0 + 4 < IMG);
    const bool col_edge = (gx0 == 0) | (gx0 + 4 == IMG);
    const bool okL      = (ry0 + ROWS < IMG);     // last pair (16) in image?

    const float* po_base = img_o + base + gx0;
    const float* pt_base = img_t + base + gx0;
    const float* poe = img_o + base + gx0 + 4;    // only deref'd when edge_ld
    const float* pte = img_t + base + gx0 + 4;
    const float2 z2 = make_float2(0.f, 0.f);

    // ---- carried diffs for current pair ----
    float4 d0, d1;
    float2 dd;
    float  eR0 = 0.f, eR1 = 0.f, eddR = 0.f;

    // prologue: pair 0 via direct LDG + convert
    {
        const size_t roff = (size_t)ry0 * IMG;
        float4 o0 = *(const float4*)(po_base + roff);
        float4 o1 = *(const float4*)(po_base + roff + IMG);
        float4 t0 = *(const float4*)(pt_base + roff);
        float4 t1 = *(const float4*)(pt_base + roff + IMG);
        d0 = make_float4(o0.x - t0.x, o0.y - t0.y, o0.z - t0.z, o0.w - t0.w);
        d1 = make_float4(o1.x - t1.x, o1.y - t1.y, o1.z - t1.z, o1.w - t1.w);
        dd.x = max4(o0.x, o0.y, o1.x, o1.y) - max4(t0.x, t0.y, t1.x, t1.y);
        dd.y = max4(o0.z, o0.w, o1.z, o1.w) - max4(t0.z, t0.w, t1.z, t1.w);
        if (edge_ld) {
            float2 a0 = *(const float2*)(poe + roff);
            float2 a1 = *(const float2*)(poe + roff + IMG);
            float2 b0 = *(const float2*)(pte + roff);
            float2 b1 = *(const float2*)(pte + roff + IMG);
            eR0  = a0.x - b0.x;
            eR1  = a1.x - b1.x;
            eddR = max4(a0.x, a0.y, a1.x, a1.y) - max4(b0.x, b0.y, b1.x, b1.y);
        }
    }

    // prologue: queue pairs 1..3 (always in image) as groups g0..g2
    #pragma unroll
    for (int p = 1; p <= 3; p++) {
        const size_t roff = (size_t)(ry0 + 2 * p) * IMG;
        cp_async16(&stg[p & 3][0][tid], po_base + roff);
        cp_async16(&stg[p & 3][1][tid], po_base + roff + IMG);
        cp_async16(&stg[p & 3][2][tid], pt_base + roff);
        cp_async16(&stg[p & 3][3][tid], pt_base + roff + IMG);
        asm volatile("cp.async.commit_group;" ::: "memory");
    }

    // packed accumulators (lo+hi summed at the end)
    const u64 zp = pk2(0.f, 0.f);
    u64 sa = zp, ca0 = zp, ca1 = zp, ca2 = zp;
    u64 sh = zp, ch0 = zp, ch1 = zp;
    float ba = 0.f, bh = 0.f;

    float4 dprev = make_float4(0.f, 0.f, 0.f, 0.f);
    float2 ddprev = z2;
    float pnd1 = 0.f, pnddx = 0.f;

    #pragma unroll 4
    for (int j = 0; j < NITER; j++) {             // pairs 0..15, all owned
        const int gy0 = ry0 + 2 * j;
        const int gy1 = gy0 + 1;

        // ---- 1. queue pair j+4 (empty commit keeps group counting uniform) ----
        {
            const int p = j + 4;
            if (p < NITER || (p == NITER && okL)) {
                const size_t roff = (size_t)(ry0 + 2 * p) * IMG;
                cp_async16(&stg[p & 3][0][tid], po_base + roff);
                cp_async16(&stg[p & 3][1][tid], po_base + roff + IMG);
                cp_async16(&stg[p & 3][2][tid], pt_base + roff);
                cp_async16(&stg[p & 3][3][tid], pt_base + roff + IMG);
            }
            asm volatile("cp.async.commit_group;" ::: "memory");
        }

        // edge raws for pair j+1 (lane 31; mostly L1/L2 hits)
        float2 ea0 = z2, ea1 = z2, eb0 = z2, eb1 = z2;
        {
            const int ng = ry0 + 2 * (j + 1);
            if (edge_ld && (j < NITER - 1 || okL)) {
                const size_t roff = (size_t)ng * IMG;
                ea0 = *(const float2*)(poe + roff);
                ea1 = *(const float2*)(poe + roff + IMG);
                eb0 = *(const float2*)(pte + roff);
                eb1 = *(const float2*)(pte + roff + IMG);
            }
        }

        // ---- 2. +1 neighbors via shuffle ----
        float t;
        t = __shfl_down_sync(0xFFFFFFFFu, d0.x, 1); float nd0  = isR ? eR0  : t;
        t = __shfl_down_sync(0xFFFFFFFFu, d1.x, 1); float nd1  = isR ? eR1  : t;
        t = __shfl_down_sync(0xFFFFFFFFu, dd.x, 1); float nddR = isR ? eddR : t;

        // ---- 3. packed FMA block (same validated math, f32x2 lanes) ----
        {
            u64 A0  = pk2(d0.x, d0.y), A1  = pk2(d0.z, d0.w);
            u64 A0s = pk2(d0.y, d0.z), A1s = pk2(d0.w, nd0);
            u64 B0  = pk2(d1.x, d1.y), B1  = pk2(d1.z, d1.w);
            u64 B0s = pk2(d1.y, d1.z), B1s = pk2(d1.w, nd1);
            u64 P0  = pk2(dprev.x, dprev.y), P1  = pk2(dprev.z, dprev.w);
            u64 P0s = pk2(dprev.y, dprev.z), P1s = pk2(dprev.w, pnd1);

            ca0 = fma2(P0,  A0,  ca0); ca0 = fma2(P1,  A1,  ca0);   // S  cross
            ca1 = fma2(P0,  A0s, ca1); ca1 = fma2(P1,  A1s, ca1);   // SE cross
            ca2 = fma2(P0s, A0,  ca2); ca2 = fma2(P1s, A1,  ca2);   // SW cross

            sa  = fma2(A0, A0, sa); sa = fma2(A1, A1, sa);
            sa  = fma2(B0, B0, sa); sa = fma2(B1, B1, sa);

            ca0 = fma2(A0,  A0s, ca0); ca0 = fma2(A1,  A1s, ca0);   // E row0
            ca1 = fma2(B0,  B0s, ca1); ca1 = fma2(B1,  B1s, ca1);   // E row1
            ca2 = fma2(A0,  B0,  ca2); ca2 = fma2(A1,  B1,  ca2);   // S pair
            ca0 = fma2(A0,  B0s, ca0); ca0 = fma2(A1,  B1s, ca0);   // SE pair
            ca1 = fma2(A0s, B0,  ca1); ca1 = fma2(A1s, B1,  ca1);   // SW pair

            u64 DD  = pk2(dd.x, dd.y);
            u64 DDs = pk2(dd.y, nddR);
            u64 PD  = pk2(ddprev.x, ddprev.y);
            u64 PDs = pk2(ddprev.y, pnddx);

            ch0 = fma2(PD,  DD,  ch0);                               // S  cross
            ch1 = fma2(PD,  DDs, ch1);                               // SE cross
            ch0 = fma2(PDs, DD,  ch0);                               // SW cross
            sh  = fma2(DD,  DD,  sh);
            ch1 = fma2(DD,  DDs, ch1);                               // E half
        }

        if (col_edge | (gy0 == 0) | (gy1 == IMG - 1)) {
            ba = fmaf(bw(gy0, gx0,     IMG) * d0.x, d0.x, ba);
            ba = fmaf(bw(gy0, gx0 + 1, IMG) * d0.y, d0.y, ba);
            ba = fmaf(bw(gy0, gx0 + 2, IMG) * d0.z, d0.z, ba);
            ba = fmaf(bw(gy0, gx0 + 3, IMG) * d0.w, d0.w, ba);
            ba = fmaf(bw(gy1, gx0,     IMG) * d1.x, d1.x, ba);
            ba = fmaf(bw(gy1, gx0 + 1, IMG) * d1.y, d1.y, ba);
            ba = fmaf(bw(gy1, gx0 + 2, IMG) * d1.z, d1.z, ba);
            ba = fmaf(bw(gy1, gx0 + 3, IMG) * d1.w, d1.w, ba);
        }
        {
            const int hgy = (ry0 >> 1) + j;
            if (col_edge | (hgy == 0) | (hgy == HIMG - 1)) {
                bh = fmaf(bw(hgy, hx0,     HIMG) * dd.x, dd.x, bh);
                bh = fmaf(bw(hgy, hx0 + 1, HIMG) * dd.y, dd.y, bh);
            }
        }

        // ---- 4. wait for pair j+1 and convert from smem ----
        asm volatile("cp.async.wait_group 3;" ::: "memory");
        float4 pd0, pd1;
        float2 pdd;
        if (j < NITER - 1 || okL) {
            const int s = (j + 1) & 3;
            float4 o0 = stg[s][0][tid], o1 = stg[s][1][tid];
            float4 t0 = stg[s][2][tid], t1 = stg[s][3][tid];
            pd0 = make_float4(o0.x - t0.x, o0.y - t0.y, o0.z - t0.z, o0.w - t0.w);
            pd1 = make_float4(o1.x - t1.x, o1.y - t1.y, o1.z - t1.z, o1.w - t1.w);
            pdd.x = max4(o0.x, o0.y, o1.x, o1.y) - max4(t0.x, t0.y, t1.x, t1.y);
            pdd.y = max4(o0.z, o0.w, o1.z, o1.w) - max4(t0.z, t0.w, t1.z, t1.w);
        } else {
            pd0 = pd1 = make_float4(0.f, 0.f, 0.f, 0.f);
            pdd = z2;
        }
        float peR0  = ea0.x - eb0.x;
        float peR1  = ea1.x - eb1.x;
        float peddR = max4(ea0.x, ea0.y, ea1.x, ea1.y)
                    - max4(eb0.x, eb0.y, eb1.x, eb1.y);

        // ---- 5. rotate ----
        dprev = d1; ddprev = dd; pnd1 = nd1; pnddx = nddR;
        d0 = pd0; d1 = pd1; dd = pdd;
        eR0 = peR0; eR1 = peR1; eddR = peddR;
    }

    // ---- peeled last pair: cross terms only (packed) ----
    {
        float t;
        t = __shfl_down_sync(0xFFFFFFFFu, d0.x, 1); float nd0  = isR ? eR0  : t;
        t = __shfl_down_sync(0xFFFFFFFFu, dd.x, 1); float nddR = isR ? eddR : t;

        u64 A0  = pk2(d0.x, d0.y), A1  = pk2(d0.z, d0.w);
        u64 A0s = pk2(d0.y, d0.z), A1s = pk2(d0.w, nd0);
        u64 P0  = pk2(dprev.x, dprev.y), P1  = pk2(dprev.z, dprev.w);
        u64 P0s = pk2(dprev.y, dprev.z), P1s = pk2(dprev.w, pnd1);

        ca0 = fma2(P0,  A0,  ca0); ca0 = fma2(P1,  A1,  ca0);   // S
        ca1 = fma2(P0,  A0s, ca1); ca1 = fma2(P1,  A1s, ca1);   // SE
        ca2 = fma2(P0s, A0,  ca2); ca2 = fma2(P1s, A1,  ca2);   // SW

        u64 DD  = pk2(dd.x, dd.y);
        u64 DDs = pk2(dd.y, nddR);
        u64 PD  = pk2(ddprev.x, ddprev.y);
        u64 PDs = pk2(ddprev.y, pnddx);
        ch0 = fma2(PD,  DD,  ch0);
        ch1 = fma2(PD,  DDs, ch1);
        ch0 = fma2(PDs, DD,  ch0);
    }

    // ---------------- block reduction + last-block finalize ----------------
    float l0, h0, l1, h1, l2, h2;
    upk2(ca0, l0, h0); upk2(ca1, l1, h1); upk2(ca2, l2, h2);
    float caf = (l0 + h0) + (l1 + h1) + (l2 + h2);
    upk2(sa, l0, h0);  float saf = l0 + h0;
    upk2(sh, l1, h1);  float shf = l1 + h1;
    upk2(ch0, l0, h0); upk2(ch1, l2, h2);
    float chf = (l0 + h0) + (l2 + h2);

    float val = (24.f * saf - ba - 4.f * caf) * WG
              + (16.f * shf - bh - 4.f * chf) * WGD;
    #pragma unroll
    for (int off = 16; off; off >>= 1)
        val += __shfl_down_sync(0xFFFFFFFFu, val, off);
    int warp = tid >> 5;
    if (lane == 0) red[warp] = val;
    __syncthreads();
    if (tid == 0) {
        float s = red[0] + red[1] + red[2] + red[3];
        int bid = (blockIdx.z * GRIDY + blockIdx.y) * 2 + blockIdx.x;
        g_part[bid] = s;
        __threadfence();
        unsigned old = atomicAdd(&g_count, 1u);
        s_last = (old == NBLK - 1) ? 1u : 0u;
    }
    __syncthreads();

    if (s_last) {
        double s = 0.0;
        #pragma unroll
        for (int i = tid; i < NBLK; i += 128)
            s += (double)g_part[i];
        #pragma unroll
        for (int off = 16; off; off >>= 1)
            s += __shfl_down_sync(0xFFFFFFFFu, s, off);
        if (lane == 0) dred[warp] = s;
        __syncthreads();
        if (tid == 0) {
            out[0] = (float)(dred[0] + dred[1] + dred[2] + dred[3]);
            g_count = 0;   // reset for next graph replay
        }
    }
}

extern "C" void kernel_launch(void* const* d_in, const int* in_sizes, int n_in,
                              void* d_out, int out_size) {
    const float* img_o = (const float*)d_in[0];
    const float* img_t = (const float*)d_in[1];
    dim3 grid(2, GRIDY, NIMG);
    gloss_corr<<<grid, 128>>>(img_o, img_t, (float*)d_out);
}

// round 17
// speedup vs baseline: 1.1233x; 1.0171x over previous
#include <cuda_runtime.h>

// GLoss fused, correlation form, bulk-TMA (cp.async.bulk + mbarrier) 4-stage
// ring, 32-row tiles. Loads bypass L1tex/LSU entirely (UBLKCP path).
//
// Identity (validated R6-R16):
//   G = 16*S - B - 4*(C_E + C_S + C_SE + C_SW),  B = sum w(p) d[p]^2,
//   w = 3*ry + 3*cx - ry*cx.  Full-res + pixel loss: WG*(24S - B - 4C).
//   Half-res: WGD*(16S - B - 4C) on dd = maxpool2(o) - maxpool2(t).
//
// Block = 128 threads = 512 cols (float4/thread), streams 17 row pairs
// (32 owned + 2 halo). Stage = one row pair of both images = 4 x 2 KB,
// loaded by tid0 via 4 cp.async.bulk into smem, completion via mbarrier
// expect_tx/complete_tx. Consumer waits parity, reads, __syncthreads,
// tid0 re-queues the freed stage for pair j+5.

#define IMG   1024
#define HIMG  512
#define NIMG  8
#define ROWS  32
#define NITER 16                      // pairs 0..15 owned
#define GRIDY (IMG / ROWS)            // 32
#define NBLK  (2 * GRIDY * NIMG)      // 512

#define WG  (1.0f / 67108864.0f)      // 1/(8*8*1024*1024)
#define WGD (1.0f / 16777216.0f)      // 1/(8*8*512*512)

#define STAGE_BYTES 8192u             // 4 rows x 2 KB
#define ROW_BYTES   2048u

__device__ float g_part[NBLK];
__device__ unsigned int g_count = 0;

__device__ __forceinline__ float bw(int y, int x, int n) {
    int ry = (y == 0) + (y == n - 1);
    int cx = (x == 0) + (x == n - 1);
    return (float)(3 * ry + 3 * cx - ry * cx);
}

__device__ __forceinline__ float max4(float a, float b, float c, float d) {
    return fmaxf(fmaxf(a, b), fmaxf(c, d));
}

__device__ __forceinline__ unsigned smem_u32(const void* p) {
    return (unsigned)__cvta_generic_to_shared(p);
}

__device__ __forceinline__ void bulk_cp2k(unsigned sdst, const void* gsrc,
                                          unsigned mbar) {
    asm volatile(
        "cp.async.bulk.shared::cta.global.mbarrier::complete_tx::bytes "
        "[%0], [%1], %2, [%3];"
        :: "r"(sdst), "l"(gsrc), "r"(ROW_BYTES), "r"(mbar) : "memory");
}

__device__ __forceinline__ void mbar_expect(unsigned mbar, unsigned bytes) {
    asm volatile("mbarrier.arrive.expect_tx.shared.b64 _, [%0], %1;"
                 :: "r"(mbar), "r"(bytes) : "memory");
}

__device__ __forceinline__ void mbar_wait(unsigned mbar, unsigned parity) {
    asm volatile(
        "{\n\t"
        ".reg .pred P;\n"
        "WAIT_%=:\n\t"
        "mbarrier.try_wait.parity.acquire.cta.shared::cta.b64 P, [%0], %1, 0x989680;\n\t"
        "@P bra.uni DONE_%=;\n\t"
        "bra.uni WAIT_%=;\n"
        "DONE_%=:\n\t"
        "}"
        :: "r"(mbar), "r"(parity) : "memory");
}

__global__ __launch_bounds__(128, 4) void gloss_corr(
    const float* __restrict__ img_o,
    const float* __restrict__ img_t,
    float* __restrict__ out)
{
    // stage slots: [stage][slot][512] floats; slot 0/1 = o rows, 2/3 = t rows.
    __shared__ float stg[4][4][512];          // 32 KB
    __shared__ unsigned long long mbar[4];
    __shared__ float red[4];
    __shared__ double dred[4];
    __shared__ unsigned int s_last;

    const int tid  = threadIdx.x;
    const int lane = tid & 31;
    const int ry0  = blockIdx.y * ROWS;
    const size_t base = (size_t)blockIdx.z * IMG * IMG;
    const int col0 = blockIdx.x * 512;            // block column origin
    const int gx0  = col0 + (tid << 2);
    const int hx0  = gx0 >> 1;

    const bool isR      = (lane == 31);
    const bool edge_ld  = isR && (gx0 + 4 < IMG);
    const bool col_edge = (gx0 == 0) | (gx0 + 4 == IMG);
    const bool okL      = (ry0 + ROWS < IMG);     // last pair (16) in image?

    const float* po_blk = img_o + base + col0;    // block-row pointers (bulk)
    const float* pt_blk = img_t + base + col0;
    const float* po_base = img_o + base + gx0;    // per-thread (prologue)
    const float* pt_base = img_t + base + gx0;
    const float* poe = img_o + base + gx0 + 4;    // only deref'd when edge_ld
    const float* pte = img_t + base + gx0 + 4;
    const float2 z2 = make_float2(0.f, 0.f);

    const unsigned mb0 = smem_u32(&mbar[0]);

    // ---- init barriers, queue stages for pairs 1..4 ----
    if (tid == 0) {
        #pragma unroll
        for (int s = 0; s < 4; s++)
            asm volatile("mbarrier.init.shared.b64 [%0], 1;"
                         :: "r"(mb0 + 8 * s) : "memory");
        asm volatile("fence.proxy.async.shared::cta;" ::: "memory");
        #pragma unroll
        for (int k = 1; k <= 4; k++) {
            const int s = k & 3;
            const unsigned mb = mb0 + 8 * s;
            const size_t roff = (size_t)(ry0 + 2 * k) * IMG;
            mbar_expect(mb, STAGE_BYTES);
            bulk_cp2k(smem_u32(&stg[s][0][0]), po_blk + roff,       mb);
            bulk_cp2k(smem_u32(&stg[s][1][0]), po_blk + roff + IMG, mb);
            bulk_cp2k(smem_u32(&stg[s][2][0]), pt_blk + roff,       mb);
            bulk_cp2k(smem_u32(&stg[s][3][0]), pt_blk + roff + IMG, mb);
        }
    }

    // ---- carried diffs for current pair ----
    float4 d0, d1;
    float2 dd;
    float  eR0 = 0.f, eR1 = 0.f, eddR = 0.f;

    // prologue: pair 0 via direct LDG + convert
    {
        const size_t roff = (size_t)ry0 * IMG;
        float4 o0 = *(const float4*)(po_base + roff);
        float4 o1 = *(const float4*)(po_base + roff + IMG);
        float4 t0 = *(const float4*)(pt_base + roff);
        float4 t1 = *(const float4*)(pt_base + roff + IMG);
        d0 = make_float4(o0.x - t0.x, o0.y - t0.y, o0.z - t0.z, o0.w - t0.w);
        d1 = make_float4(o1.x - t1.x, o1.y - t1.y, o1.z - t1.z, o1.w - t1.w);
        dd.x = max4(o0.x, o0.y, o1.x, o1.y) - max4(t0.x, t0.y, t1.x, t1.y);
        dd.y = max4(o0.z, o0.w, o1.z, o1.w) - max4(t0.z, t0.w, t1.z, t1.w);
        if (edge_ld) {
            float2 a0 = *(const float2*)(poe + roff);
            float2 a1 = *(const float2*)(poe + roff + IMG);
            float2 b0 = *(const float2*)(pte + roff);
            float2 b1 = *(const float2*)(pte + roff + IMG);
            eR0  = a0.x - b0.x;
            eR1  = a1.x - b1.x;
            eddR = max4(a0.x, a0.y, a1.x, a1.y) - max4(b0.x, b0.y, b1.x, b1.y);
        }
    }
    __syncthreads();   // barriers initialized before anyone waits

    float sa = 0.f, ca0 = 0.f, ca1 = 0.f, ca2 = 0.f, ba = 0.f;
    float sh = 0.f, ch0 = 0.f, ch1 = 0.f, bh = 0.f;
    float4 dprev = make_float4(0.f, 0.f, 0.f, 0.f);
    float2 ddprev = z2;
    float pnd1 = 0.f, pnddx = 0.f;

    #pragma unroll 4
    for (int j = 0; j < NITER; j++) {             // pairs 0..15, all owned
        const int gy0 = ry0 + 2 * j;
        const int gy1 = gy0 + 1;
        const int k   = j + 1;                    // pair consumed this iter
        const int s   = k & 3;
        const unsigned ph = (unsigned)(((k >> 2) + ((k & 3) == 0)) & 1);

        // edge raws for pair j+1 (lane 31; mostly L1/L2 hits)
        float2 ea0 = z2, ea1 = z2, eb0 = z2, eb1 = z2;
        {
            const int ng = ry0 + 2 * k;
            if (edge_ld && (j < NITER - 1 || okL)) {
                const size_t roff = (size_t)ng * IMG;
                ea0 = *(const float2*)(poe + roff);
                ea1 = *(const float2*)(poe + roff + IMG);
                eb0 = *(const float2*)(pte + roff);
                eb1 = *(const float2*)(pte + roff + IMG);
            }
        }

        // ---- +1 neighbors via shuffle ----
        float t;
        t = __shfl_down_sync(0xFFFFFFFFu, d0.x, 1); float nd0  = isR ? eR0  : t;
        t = __shfl_down_sync(0xFFFFFFFFu, d1.x, 1); float nd1  = isR ? eR1  : t;
        t = __shfl_down_sync(0xFFFFFFFFu, dd.x, 1); float nddR = isR ? eddR : t;

        // ---- FMA block (validated math) ----
        ca0 = fmaf(dprev.x, d0.x, ca0); ca0 = fmaf(dprev.y, d0.y, ca0);   // S
        ca0 = fmaf(dprev.z, d0.z, ca0); ca0 = fmaf(dprev.w, d0.w, ca0);
        ca1 = fmaf(dprev.x, d0.y, ca1); ca1 = fmaf(dprev.y, d0.z, ca1);   // SE
        ca1 = fmaf(dprev.z, d0.w, ca1); ca1 = fmaf(dprev.w, nd0,  ca1);
        ca2 = fmaf(dprev.y, d0.x, ca2); ca2 = fmaf(dprev.z, d0.y, ca2);   // SW
        ca2 = fmaf(dprev.w, d0.z, ca2); ca2 = fmaf(pnd1,    d0.w, ca2);

        ch0 = fmaf(ddprev.x, dd.x, ch0); ch0 = fmaf(ddprev.y, dd.y, ch0); // S
        ch1 = fmaf(ddprev.x, dd.y, ch1); ch1 = fmaf(ddprev.y, nddR, ch1); // SE
        ch0 = fmaf(ddprev.y, dd.x, ch0); ch0 = fmaf(pnddx,    dd.y, ch0); // SW

        sa = fmaf(d0.x, d0.x, sa); sa = fmaf(d0.y, d0.y, sa);
        sa = fmaf(d0.z, d0.z, sa); sa = fmaf(d0.w, d0.w, sa);
        sa = fmaf(d1.x, d1.x, sa); sa = fmaf(d1.y, d1.y, sa);
        sa = fmaf(d1.z, d1.z, sa); sa = fmaf(d1.w, d1.w, sa);

        ca0 = fmaf(d0.x, d0.y, ca0); ca0 = fmaf(d0.y, d0.z, ca0);        // E row0
        ca0 = fmaf(d0.z, d0.w, ca0); ca0 = fmaf(d0.w, nd0,  ca0);
        ca1 = fmaf(d1.x, d1.y, ca1); ca1 = fmaf(d1.y, d1.z, ca1);        // E row1
        ca1 = fmaf(d1.z, d1.w, ca1); ca1 = fmaf(d1.w, nd1,  ca1);
        ca2 = fmaf(d0.x, d1.x, ca2); ca2 = fmaf(d0.y, d1.y, ca2);        // S pair
        ca2 = fmaf(d0.z, d1.z, ca2); ca2 = fmaf(d0.w, d1.w, ca2);
        ca0 = fmaf(d0.x, d1.y, ca0); ca0 = fmaf(d0.y, d1.z, ca0);        // SE pair
        ca0 = fmaf(d0.z, d1.w, ca0); ca0 = fmaf(d0.w, nd1,  ca0);
        ca1 = fmaf(d0.y, d1.x, ca1); ca1 = fmaf(d0.z, d1.y, ca1);        // SW pair
        ca1 = fmaf(d0.w, d1.z, ca1); ca1 = fmaf(nd0,  d1.w, ca1);

        sh  = fmaf(dd.x, dd.x, sh);  sh  = fmaf(dd.y, dd.y, sh);
        ch1 = fmaf(dd.x, dd.y, ch1); ch1 = fmaf(dd.y, nddR, ch1);        // E half

        if (col_edge | (gy0 == 0) | (gy1 == IMG - 1)) {
            ba = fmaf(bw(gy0, gx0,     IMG) * d0.x, d0.x, ba);
            ba = fmaf(bw(gy0, gx0 + 1, IMG) * d0.y, d0.y, ba);
            ba = fmaf(bw(gy0, gx0 + 2, IMG) * d0.z, d0.z, ba);
            ba = fmaf(bw(gy0, gx0 + 3, IMG) * d0.w, d0.w, ba);
            ba = fmaf(bw(gy1, gx0,     IMG) * d1.x, d1.x, ba);
            ba = fmaf(bw(gy1, gx0 + 1, IMG) * d1.y, d1.y, ba);
            ba = fmaf(bw(gy1, gx0 + 2, IMG) * d1.z, d1.z, ba);
            ba = fmaf(bw(gy1, gx0 + 3, IMG) * d1.w, d1.w, ba);
        }
        {
            const int hgy = (ry0 >> 1) + j;
            if (col_edge | (hgy == 0) | (hgy == HIMG - 1)) {
                bh = fmaf(bw(hgy, hx0,     HIMG) * dd.x, dd.x, bh);
                bh = fmaf(bw(hgy, hx0 + 1, HIMG) * dd.y, dd.y, bh);
            }
        }

        // ---- wait for pair j+1 (mbarrier), read raws from smem ----
        mbar_wait(mb0 + 8 * s, ph);
        float4 o0 = *(const float4*)&stg[s][0][tid << 2];
        float4 o1 = *(const float4*)&stg[s][1][tid << 2];
        float4 t0 = *(const float4*)&stg[s][2][tid << 2];
        float4 t1 = *(const float4*)&stg[s][3][tid << 2];
        __syncthreads();   // all warps done reading stage s

        // ---- tid0 re-queues stage s for pair j+5 (clamped row; masked later) ----
        if (tid == 0 && j + 5 <= NITER) {
            int gy = ry0 + 2 * (j + 5);
            if (gy > IMG - 2) gy = IMG - 2;       // clamp (garbage masked)
            const size_t roff = (size_t)gy * IMG;
            const unsigned mb = mb0 + 8 * s;
            asm volatile("fence.proxy.async.shared::cta;" ::: "memory");
            mbar_expect(mb, STAGE_BYTES);
            bulk_cp2k(smem_u32(&stg[s][0][0]), po_blk + roff,       mb);
            bulk_cp2k(smem_u32(&stg[s][1][0]), po_blk + roff + IMG, mb);
            bulk_cp2k(smem_u32(&stg[s][2][0]), pt_blk + roff,       mb);
            bulk_cp2k(smem_u32(&stg[s][3][0]), pt_blk + roff + IMG, mb);
        }

        // ---- convert raws -> next pair diffs (masked on bottom tile) ----
        float4 pd0, pd1;
        float2 pdd;
        if (j < NITER - 1 || okL) {
            pd0 = make_float4(o0.x - t0.x, o0.y - t0.y, o0.z - t0.z, o0.w - t0.w);
            pd1 = make_float4(o1.x - t1.x, o1.y - t1.y, o1.z - t1.z, o1.w - t1.w);
            pdd.x = max4(o0.x, o0.y, o1.x, o1.y) - max4(t0.x, t0.y, t1.x, t1.y);
            pdd.y = max4(o0.z, o0.w, o1.z, o1.w) - max4(t0.z, t0.w, t1.z, t1.w);
        } else {
            pd0 = pd1 = make_float4(0.f, 0.f, 0.f, 0.f);
            pdd = z2;
        }
        float peR0  = ea0.x - eb0.x;
        float peR1  = ea1.x - eb1.x;
        float peddR = max4(ea0.x, ea0.y, ea1.x, ea1.y)
                    - max4(eb0.x, eb0.y, eb1.x, eb1.y);

        // ---- rotate ----
        dprev = d1; ddprev = dd; pnd1 = nd1; pnddx = nddR;
        d0 = pd0; d1 = pd1; dd = pdd;
        eR0 = peR0; eR1 = peR1; eddR = peddR;
    }

    // ---- peeled last pair: cross terms only ----
    {
        float t;
        t = __shfl_down_sync(0xFFFFFFFFu, d0.x, 1); float nd0  = isR ? eR0  : t;
        t = __shfl_down_sync(0xFFFFFFFFu, dd.x, 1); float nddR = isR ? eddR : t;

        ca0 = fmaf(dprev.x, d0.x, ca0); ca0 = fmaf(dprev.y, d0.y, ca0);   // S
        ca0 = fmaf(dprev.z, d0.z, ca0); ca0 = fmaf(dprev.w, d0.w, ca0);
        ca1 = fmaf(dprev.x, d0.y, ca1); ca1 = fmaf(dprev.y, d0.z, ca1);   // SE
        ca1 = fmaf(dprev.z, d0.w, ca1); ca1 = fmaf(dprev.w, nd0,  ca1);
        ca2 = fmaf(dprev.y, d0.x, ca2); ca2 = fmaf(dprev.z, d0.y, ca2);   // SW
        ca2 = fmaf(dprev.w, d0.z, ca2); ca2 = fmaf(pnd1,    d0.w, ca2);

        ch0 = fmaf(ddprev.x, dd.x, ch0); ch0 = fmaf(ddprev.y, dd.y, ch0); // S
        ch1 = fmaf(ddprev.x, dd.y, ch1); ch1 = fmaf(ddprev.y, nddR, ch1); // SE
        ch0 = fmaf(ddprev.y, dd.x, ch0); ch0 = fmaf(pnddx,    dd.y, ch0); // SW
    }

    // ---------------- block reduction + last-block finalize ----------------
    float ca = ca0 + ca1 + ca2;
    float ch = ch0 + ch1;
    float val = (24.f * sa - ba - 4.f * ca) * WG
              + (16.f * sh - bh - 4.f * ch) * WGD;
    #pragma unroll
    for (int off = 16; off; off >>= 1)
        val += __shfl_down_sync(0xFFFFFFFFu, val, off);
    int warp = tid >> 5;
    if (lane == 0) red[warp] = val;
    __syncthreads();
    if (tid == 0) {
        float s = red[0] + red[1] + red[2] + red[3];
        int bid = (blockIdx.z * GRIDY + blockIdx.y) * 2 + blockIdx.x;
        g_part[bid] = s;
        __threadfence();
        unsigned old = atomicAdd(&g_count, 1u);
        s_last = (old == NBLK - 1) ? 1u : 0u;
    }
    __syncthreads();

    if (s_last) {
        double s = 0.0;
        #pragma unroll
        for (int i = tid; i < NBLK; i += 128)
            s += (double)g_part[i];
        #pragma unroll
        for (int off = 16; off; off >>= 1)
            s += __shfl_down_sync(0xFFFFFFFFu, s, off);
        if (lane == 0) dred[warp] = s;
        __syncthreads();
        if (tid == 0) {
            out[0] = (float)(dred[0] + dred[1] + dred[2] + dred[3]);
            g_count = 0;   // reset for next graph replay
        }
    }
}

extern "C" void kernel_launch(void* const* d_in, const int* in_sizes, int n_in,
                              void* d_out, int out_size) {
    const float* img_o = (const float*)d_in[0];
    const float* img_t = (const float*)d_in[1];
    dim3 grid(2, GRIDY, NIMG);
    gloss_corr<<<grid, 128>>>(img_o, img_t, (float*)d_out);
}